// round 2
// baseline (speedup 1.0000x reference)
#include <cuda_runtime.h>

#define BB 2
#define NN 16384
#define KK 16
#define CC 64
#define AA 8
#define PTS (BB*NN)          // 32768 points
#define ITEMS (PTS*KK)       // 524288 (b,n,k) items

// ---------------- scratch (device globals; no allocation allowed) ----------
__device__ float  g_q [PTS*CC];
__device__ float  g_k [PTS*CC];
__device__ float  g_v [PTS*CC];
__device__ float  g_d1[ITEMS*3];
__device__ float  g_h1[ITEMS*AA];
// acc layout: [0..2]=d_sum [3..5]=d_sq [6..69]=g1_sum [70..133]=g1_sq
//             [134..141]=g2_sum [142..149]=g2_sq
__device__ double g_acc[150];
// bn layout:  [0..2]=a_d [3..5]=b_d [6..69]=a1 [70..133]=b1 [134..141]=a2 [142..149]=b2
__device__ float  g_bn[150];

// ---------------- kernel 0: zero accumulators ------------------------------
__global__ void k_zero() {
    int i = threadIdx.x;
    if (i < 150) g_acc[i] = 0.0;
}

// ---------------- kernel 1: q/k/v linear (tiled GEMM) ----------------------
__global__ void k_qkv(const float* __restrict__ feat,
                      const float* __restrict__ Wq, const float* __restrict__ bq,
                      const float* __restrict__ Wk, const float* __restrict__ bk,
                      const float* __restrict__ Wv, const float* __restrict__ bv) {
    __shared__ float sF[64][65];
    __shared__ float sW[64][64];
    const int t   = threadIdx.x;        // 256
    const int col = t & 63;
    const int r0  = t >> 6;             // 0..3
    for (int tile = blockIdx.x; tile < PTS/64; tile += gridDim.x) {
        const int rowBase = tile * 64;
        for (int i = t; i < 4096; i += 256) sF[i>>6][i&63] = feat[rowBase*64 + i];
        __syncthreads();
        for (int m = 0; m < 3; m++) {
            const float* W    = (m==0) ? Wq : ((m==1) ? Wk : Wv);
            const float* bptr = (m==0) ? bq : ((m==1) ? bk : bv);
            float* outp       = (m==0) ? g_q : ((m==1) ? g_k : g_v);
            for (int i = t; i < 4096; i += 256) sW[i>>6][i&63] = W[i];
            __syncthreads();
            const float bias = bptr[col];
            float acc[16];
            #pragma unroll
            for (int j2 = 0; j2 < 16; j2++) acc[j2] = bias;
            #pragma unroll
            for (int i = 0; i < 64; i++) {
                const float wv = sW[i][col];
                #pragma unroll
                for (int j2 = 0; j2 < 16; j2++) acc[j2] += sF[r0 + 4*j2][i] * wv;
            }
            #pragma unroll
            for (int j2 = 0; j2 < 16; j2++)
                outp[(rowBase + r0 + 4*j2)*CC + col] = acc[j2];
            __syncthreads();
        }
    }
}

// ---------------- kernel 2: d1 = rel @ Wd1 + bd1, plus stats ---------------
__global__ void k_d1(const float* __restrict__ xyz, const int* __restrict__ knn,
                     const float* __restrict__ Wd1, const float* __restrict__ bd1) {
    float w[9], bb[3];
    #pragma unroll
    for (int i = 0; i < 9; i++) w[i] = Wd1[i];
    #pragma unroll
    for (int i = 0; i < 3; i++) bb[i] = bd1[i];
    float s[3] = {0,0,0}, qq[3] = {0,0,0};
    const int stride = gridDim.x * blockDim.x;
    for (int id = blockIdx.x*blockDim.x + threadIdx.x; id < ITEMS; id += stride) {
        const int p = id >> 4;
        const int b = p >> 14;
        const int n = p & (NN-1);
        const int j = knn[id];
        const float* xc = xyz + (b*NN + n)*3;
        const float* xn = xyz + (b*NN + j)*3;
        const float r0 = xc[0]-xn[0], r1 = xc[1]-xn[1], r2 = xc[2]-xn[2];
        #pragma unroll
        for (int c = 0; c < 3; c++) {
            const float d = r0*w[c] + r1*w[3+c] + r2*w[6+c] + bb[c];
            g_d1[id*3 + c] = d;
            s[c] += d; qq[c] += d*d;
        }
    }
    #pragma unroll
    for (int c = 0; c < 3; c++) {
        #pragma unroll
        for (int off = 16; off; off >>= 1) {
            s[c]  += __shfl_xor_sync(0xFFFFFFFFu, s[c],  off);
            qq[c] += __shfl_xor_sync(0xFFFFFFFFu, qq[c], off);
        }
    }
    if ((threadIdx.x & 31) == 0) {
        #pragma unroll
        for (int c = 0; c < 3; c++) {
            atomicAdd(&g_acc[c],     (double)s[c]);
            atomicAdd(&g_acc[3 + c], (double)qq[c]);
        }
    }
}

// ---------------- generic BN finalize --------------------------------------
__global__ void k_fin(int nch, int accOff, int bnOff,
                      const float* __restrict__ gamma, const float* __restrict__ beta) {
    const int c = threadIdx.x;
    if (c < nch) {
        const double inv = 1.0 / (double)ITEMS;
        const double m = g_acc[accOff + c] * inv;
        const double v = g_acc[accOff + nch + c] * inv - m*m;
        const float a = gamma[c] * rsqrtf((float)v + 1e-5f);
        g_bn[bnOff + c]       = a;
        g_bn[bnOff + nch + c] = beta[c] - (float)m * a;
    }
}

// ---------------- kernel 3: attn_in stats (64 channels) --------------------
__global__ void k_g1s(const int* __restrict__ knn, const float* __restrict__ Wd2,
                      const float* __restrict__ bd2p) {
    const int lane = threadIdx.x & 31;
    const int warp = (blockIdx.x*blockDim.x + threadIdx.x) >> 5;
    const int nw   = (gridDim.x*blockDim.x) >> 5;
    const int c0 = lane, c1 = lane + 32;
    const float ad0=g_bn[0], ad1=g_bn[1], ad2=g_bn[2];
    const float bd0=g_bn[3], bd1v=g_bn[4], bd2v=g_bn[5];
    const float w00=Wd2[c0], w10=Wd2[64+c0], w20=Wd2[128+c0], bb0=bd2p[c0];
    const float w01=Wd2[c1], w11=Wd2[64+c1], w21=Wd2[128+c1], bb1=bd2p[c1];
    float s0=0, s1=0, q0=0, q1=0;
    for (int p = warp; p < PTS; p += nw) {
        const int b = p >> 14;
        const float qa = g_q[p*CC + c0], qb = g_q[p*CC + c1];
        const int* kn = knn + p*KK;
        const float* dp = g_d1 + p*KK*3;
        #pragma unroll 4
        for (int k = 0; k < KK; k++) {
            const int j = kn[k];
            const float t0 = fmaxf(ad0*dp[k*3+0] + bd0,  0.f);
            const float t1 = fmaxf(ad1*dp[k*3+1] + bd1v, 0.f);
            const float t2 = fmaxf(ad2*dp[k*3+2] + bd2v, 0.f);
            const float* kr = g_k + ((b<<14) + j)*CC;
            const float x0 = qa - kr[c0] + t0*w00 + t1*w10 + t2*w20 + bb0;
            const float x1 = qb - kr[c1] + t0*w01 + t1*w11 + t2*w21 + bb1;
            s0 += x0; q0 += x0*x0; s1 += x1; q1 += x1*x1;
        }
    }
    atomicAdd(&g_acc[6  + c0], (double)s0);
    atomicAdd(&g_acc[6  + c1], (double)s1);
    atomicAdd(&g_acc[70 + c0], (double)q0);
    atomicAdd(&g_acc[70 + c1], (double)q1);
}

// ---------------- kernel 4: h1 = relu(bn(attn_in))@Wg1+bg1, plus g2 stats --
__global__ void k_h1(const int* __restrict__ knn, const float* __restrict__ Wd2,
                     const float* __restrict__ bd2p, const float* __restrict__ Wg1,
                     const float* __restrict__ bg1) {
    const int lane = threadIdx.x & 31;
    const int warp = (blockIdx.x*blockDim.x + threadIdx.x) >> 5;
    const int nw   = (gridDim.x*blockDim.x) >> 5;
    const int c0 = lane, c1 = lane + 32;
    const float ad0=g_bn[0], ad1=g_bn[1], ad2=g_bn[2];
    const float bd0=g_bn[3], bd1v=g_bn[4], bd2v=g_bn[5];
    const float w00=Wd2[c0], w10=Wd2[64+c0], w20=Wd2[128+c0], bb0=bd2p[c0];
    const float w01=Wd2[c1], w11=Wd2[64+c1], w21=Wd2[128+c1], bb1=bd2p[c1];
    const float a1c0 = g_bn[6+c0],  a1c1 = g_bn[6+c1];
    const float b1c0 = g_bn[70+c0], b1c1 = g_bn[70+c1];
    float wgA[8], wgB[8];
    #pragma unroll
    for (int a = 0; a < 8; a++) { wgA[a] = Wg1[c0*8+a]; wgB[a] = Wg1[c1*8+a]; }
    const float bgl = (lane < 8) ? bg1[lane] : 0.f;
    float s2 = 0.f, q2 = 0.f;
    for (int p = warp; p < PTS; p += nw) {
        const int b = p >> 14;
        const float qa = g_q[p*CC + c0], qb = g_q[p*CC + c1];
        const int* kn = knn + p*KK;
        const float* dp = g_d1 + p*KK*3;
        for (int k = 0; k < KK; k++) {
            const int j = kn[k];
            const float t0 = fmaxf(ad0*dp[k*3+0] + bd0,  0.f);
            const float t1 = fmaxf(ad1*dp[k*3+1] + bd1v, 0.f);
            const float t2 = fmaxf(ad2*dp[k*3+2] + bd2v, 0.f);
            const float* kr = g_k + ((b<<14) + j)*CC;
            const float x0 = qa - kr[c0] + t0*w00 + t1*w10 + t2*w20 + bb0;
            const float x1 = qb - kr[c1] + t0*w01 + t1*w11 + t2*w21 + bb1;
            const float y0 = fmaxf(a1c0*x0 + b1c0, 0.f);
            const float y1 = fmaxf(a1c1*x1 + b1c1, 0.f);
            float part[8];
            #pragma unroll
            for (int a = 0; a < 8; a++) part[a] = y0*wgA[a] + y1*wgB[a];
            #pragma unroll
            for (int off = 16; off; off >>= 1)
                #pragma unroll
                for (int a = 0; a < 8; a++)
                    part[a] += __shfl_xor_sync(0xFFFFFFFFu, part[a], off);
            if (lane < 8) {
                const float h = part[lane] + bgl;
                g_h1[(p*KK + k)*AA + lane] = h;
                s2 += h; q2 += h*h;
            }
        }
    }
    if (lane < 8) {
        atomicAdd(&g_acc[134 + lane], (double)s2);
        atomicAdd(&g_acc[142 + lane], (double)q2);
    }
}

// ---------------- kernel 5: h2, softmax, weighted aggregation --------------
__global__ void k_final(const int* __restrict__ knn, const float* __restrict__ Wd2,
                        const float* __restrict__ bd2p, const float* __restrict__ Wg2,
                        const float* __restrict__ bg2, float* __restrict__ out) {
    __shared__ float sWg2[64], sa2[8], sb2[8], sbg2[8];
    __shared__ float sattn[8][16][8];
    __shared__ float st[8][16][3];
    __shared__ int   sidx[8][16];
    const int t = threadIdx.x;
    if (t < 64) sWg2[t] = Wg2[t];
    if (t < 8) { sa2[t] = g_bn[134+t]; sb2[t] = g_bn[142+t]; sbg2[t] = bg2[t]; }
    __syncthreads();
    const int lane = t & 31, w = t >> 5;
    const int nw   = (gridDim.x * blockDim.x) >> 5;
    int warp = (blockIdx.x * blockDim.x + t) >> 5;
    const int c0 = lane, c1 = lane + 32;
    const float ad0=g_bn[0], ad1=g_bn[1], ad2=g_bn[2];
    const float bd0=g_bn[3], bd1v=g_bn[4], bd2v=g_bn[5];
    const float w00=Wd2[c0], w10=Wd2[64+c0], w20=Wd2[128+c0], bb0=bd2p[c0];
    const float w01=Wd2[c1], w11=Wd2[64+c1], w21=Wd2[128+c1], bb1=bd2p[c1];
    const int a = lane & 7;
    for (int p = warp; p < PTS; p += nw) {
        const int b = p >> 14;
        if (lane < 16) {
            const int k = lane;
            const int j = knn[p*KK + k];
            sidx[w][k] = j;
            const float* hp = g_h1 + (p*KK + k)*AA;
            float h2[8];
            {
                float z[8];
                #pragma unroll
                for (int x = 0; x < 8; x++) z[x] = fmaxf(sa2[x]*hp[x] + sb2[x], 0.f);
                #pragma unroll
                for (int x = 0; x < 8; x++) {
                    float acc = sbg2[x];
                    #pragma unroll
                    for (int jj = 0; jj < 8; jj++) acc += z[jj]*sWg2[jj*8 + x];
                    h2[x] = acc;
                }
            }
            float mx[8];
            #pragma unroll
            for (int x = 0; x < 8; x++) mx[x] = h2[x];
            #pragma unroll
            for (int off = 8; off; off >>= 1)
                #pragma unroll
                for (int x = 0; x < 8; x++)
                    mx[x] = fmaxf(mx[x], __shfl_xor_sync(0x0000FFFFu, mx[x], off, 16));
            float ex[8], sm[8];
            #pragma unroll
            for (int x = 0; x < 8; x++) { ex[x] = expf(h2[x] - mx[x]); sm[x] = ex[x]; }
            #pragma unroll
            for (int off = 8; off; off >>= 1)
                #pragma unroll
                for (int x = 0; x < 8; x++)
                    sm[x] += __shfl_xor_sync(0x0000FFFFu, sm[x], off, 16);
            #pragma unroll
            for (int x = 0; x < 8; x++) sattn[w][k][x] = ex[x] / sm[x];
            const float* dpp = g_d1 + (p*KK + k)*3;
            st[w][k][0] = fmaxf(ad0*dpp[0] + bd0,  0.f);
            st[w][k][1] = fmaxf(ad1*dpp[1] + bd1v, 0.f);
            st[w][k][2] = fmaxf(ad2*dpp[2] + bd2v, 0.f);
        }
        __syncwarp();
        float acc0 = 0.f, acc1 = 0.f;
        #pragma unroll
        for (int k = 0; k < KK; k++) {
            const int j = sidx[w][k];
            const float* vr = g_v + ((b<<14) + j)*CC;
            const float t0 = st[w][k][0], t1 = st[w][k][1], t2 = st[w][k][2];
            const float at = sattn[w][k][a];
            acc0 += (vr[c0] + t0*w00 + t1*w10 + t2*w20 + bb0) * at;
            acc1 += (vr[c1] + t0*w01 + t1*w11 + t2*w21 + bb1) * at;
        }
        out[p*CC + c0] = acc0;
        out[p*CC + c1] = acc1;
        __syncwarp();
    }
}

// ---------------- launch ----------------------------------------------------
extern "C" void kernel_launch(void* const* d_in, const int* in_sizes, int n_in,
                              void* d_out, int out_size) {
    const float* xyz  = (const float*)d_in[0];
    const float* feat = (const float*)d_in[1];
    const int*   knn  = (const int*)  d_in[2];
    const float* Wq   = (const float*)d_in[3];  const float* bq  = (const float*)d_in[4];
    const float* Wk   = (const float*)d_in[5];  const float* bk  = (const float*)d_in[6];
    const float* Wv   = (const float*)d_in[7];  const float* bv  = (const float*)d_in[8];
    const float* Wd1  = (const float*)d_in[9];  const float* bd1 = (const float*)d_in[10];
    const float* gd   = (const float*)d_in[11]; const float* bed = (const float*)d_in[12];
    const float* Wd2  = (const float*)d_in[13]; const float* bd2 = (const float*)d_in[14];
    const float* g1   = (const float*)d_in[15]; const float* be1 = (const float*)d_in[16];
    const float* Wg1  = (const float*)d_in[17]; const float* bg1 = (const float*)d_in[18];
    const float* g2   = (const float*)d_in[19]; const float* be2 = (const float*)d_in[20];
    const float* Wg2  = (const float*)d_in[21]; const float* bg2 = (const float*)d_in[22];
    float* out = (float*)d_out;

    k_zero <<<1, 192>>>();
    k_qkv  <<<512, 256>>>(feat, Wq, bq, Wk, bk, Wv, bv);
    k_d1   <<<512, 256>>>(xyz, knn, Wd1, bd1);
    k_fin  <<<1, 64>>>(3, 0, 0, gd, bed);
    k_g1s  <<<512, 256>>>(knn, Wd2, bd2);
    k_fin  <<<1, 64>>>(64, 6, 6, g1, be1);
    k_h1   <<<512, 256>>>(knn, Wd2, bd2, Wg1, bg1);
    k_fin  <<<1, 64>>>(8, 134, 134, g2, be2);
    k_final<<<512, 256>>>(knn, Wd2, bd2, Wg2, bg2, out);
}